// round 1
// baseline (speedup 1.0000x reference)
#include <cuda_runtime.h>

#define N_NODES 100000
#define N_EDGES 1200000
#define NF 64
#define NG 64

// ---- persistent device scratch (no runtime allocation allowed) ----
__device__ float g_deg[N_NODES];
__device__ float g_hs [N_NODES * NF];   // dinv-scaled X@W (gather source)
__device__ float g_acc[N_NODES * NF];   // aggregation target (init = self-loop term)
__device__ float g_h1 [N_NODES * NF];   // layer-1 activations

__device__ __forceinline__ void red_add_v4(float* p, float4 v) {
    asm volatile("red.global.add.v4.f32 [%0], {%1,%2,%3,%4};"
                 :: "l"(p), "f"(v.x), "f"(v.y), "f"(v.z), "f"(v.w) : "memory");
}

// deg = 1 (self loop); zero the pooled region of d_out
__global__ void k_init(float* __restrict__ pooled) {
    int i = blockIdx.x * blockDim.x + threadIdx.x;
    if (i < N_NODES) g_deg[i] = 1.0f;
    if (i < NG * 128) pooled[i] = 0.0f;
}

__global__ void k_deg(const int* __restrict__ ei) {
    int e = blockIdx.x * blockDim.x + threadIdx.x;
    if (e < N_EDGES) atomicAdd(&g_deg[ei[N_EDGES + e]], 1.0f);
}

// hs[n][j] = acc[n][j] = dinv[n] * sum_k X[n][k] * W[k][j]
// 64 rows per block, 256 threads, 4x4 register tile per thread.
template<int LAYER>
__global__ __launch_bounds__(256) void k_gemm(const float* __restrict__ Xin,
                                              const float* __restrict__ W) {
    __shared__ float sW [64 * 64];   // sW[k*64 + j]
    __shared__ float sXT[64 * 65];   // sXT[k*65 + r]  (padded: conflict-free)
    const float* __restrict__ X = (LAYER == 0) ? Xin : (const float*)g_h1;

    const int t = threadIdx.x;
    const int rowBase = blockIdx.x * 64;

    #pragma unroll
    for (int i = 0; i < 16; i++) sW[t + i * 256] = W[t + i * 256];

    #pragma unroll
    for (int i = 0; i < 16; i++) {
        int flat = t + i * 256;
        int r = flat >> 6, k = flat & 63;
        int row = rowBase + r;
        sXT[k * 65 + r] = (row < N_NODES) ? X[row * 64 + k] : 0.0f;
    }
    __syncthreads();

    const int jq = t & 15;   // output quad: j = jq*4 .. jq*4+3
    const int rg = t >> 4;   // row group:   r = rg*4 .. rg*4+3

    float a00=0.f,a01=0.f,a02=0.f,a03=0.f;
    float a10=0.f,a11=0.f,a12=0.f,a13=0.f;
    float a20=0.f,a21=0.f,a22=0.f,a23=0.f;
    float a30=0.f,a31=0.f,a32=0.f,a33=0.f;

    const float4* sW4 = reinterpret_cast<const float4*>(sW);
    #pragma unroll 16
    for (int k = 0; k < 64; k++) {
        float4 wv = sW4[k * 16 + jq];
        const float* xp = &sXT[k * 65 + rg * 4];
        float x0 = xp[0], x1 = xp[1], x2 = xp[2], x3 = xp[3];
        a00 += x0 * wv.x; a01 += x0 * wv.y; a02 += x0 * wv.z; a03 += x0 * wv.w;
        a10 += x1 * wv.x; a11 += x1 * wv.y; a12 += x1 * wv.z; a13 += x1 * wv.w;
        a20 += x2 * wv.x; a21 += x2 * wv.y; a22 += x2 * wv.z; a23 += x2 * wv.w;
        a30 += x3 * wv.x; a31 += x3 * wv.y; a32 += x3 * wv.z; a33 += x3 * wv.w;
    }

    float r0[4] = {a00,a01,a02,a03};
    float r1[4] = {a10,a11,a12,a13};
    float r2[4] = {a20,a21,a22,a23};
    float r3[4] = {a30,a31,a32,a33};
    float* rows[4] = {r0, r1, r2, r3};

    #pragma unroll
    for (int a = 0; a < 4; a++) {
        int row = rowBase + rg * 4 + a;
        if (row < N_NODES) {
            float dinv = rsqrtf(g_deg[row]);
            float4 o = make_float4(rows[a][0] * dinv, rows[a][1] * dinv,
                                   rows[a][2] * dinv, rows[a][3] * dinv);
            *reinterpret_cast<float4*>(&g_hs [row * 64 + jq * 4]) = o;
            *reinterpret_cast<float4*>(&g_acc[row * 64 + jq * 4]) = o;
        }
    }
}

// acc[dst] += hs[src]; 16 float4 lanes per edge, v4 reductions.
__global__ void k_scatter(const int* __restrict__ ei) {
    int idx = blockIdx.x * blockDim.x + threadIdx.x;
    if (idx >= N_EDGES * 16) return;
    int e = idx >> 4;
    int c = idx & 15;
    int s = ei[e];
    int d = ei[N_EDGES + e];
    float4 v = *reinterpret_cast<const float4*>(&g_hs[s * 64 + c * 4]);
    red_add_v4(&g_acc[d * 64 + c * 4], v);
}

// h = relu(dinv*acc + b); write activations; pool via sorted-batch running sum.
template<int LAYER>
__global__ __launch_bounds__(256) void k_finalize(const float* __restrict__ bias,
                                                  const int* __restrict__ batch,
                                                  float* __restrict__ h2out,
                                                  float* __restrict__ pooled) {
    const int fq   = threadIdx.x & 15;   // feature quad
    const int lane = threadIdx.x >> 4;   // 16 node lanes
    const int start = blockIdx.x * 256;
    float* __restrict__ out = (LAYER == 0) ? (float*)g_h1 : h2out;

    const float4 b4 = reinterpret_cast<const float4*>(bias)[fq];
    float4 sum = make_float4(0.f, 0.f, 0.f, 0.f);
    int cur = -1;

    #pragma unroll 4
    for (int i = 0; i < 16; i++) {
        int n = start + lane + i * 16;
        if (n < N_NODES) {
            float dinv = rsqrtf(g_deg[n]);
            float4 a = *reinterpret_cast<const float4*>(&g_acc[n * 64 + fq * 4]);
            float4 h;
            h.x = fmaxf(fmaf(a.x, dinv, b4.x), 0.f);
            h.y = fmaxf(fmaf(a.y, dinv, b4.y), 0.f);
            h.z = fmaxf(fmaf(a.z, dinv, b4.z), 0.f);
            h.w = fmaxf(fmaf(a.w, dinv, b4.w), 0.f);
            *reinterpret_cast<float4*>(&out[n * 64 + fq * 4]) = h;

            int g = batch[n];
            if (g != cur) {
                if (cur >= 0)
                    red_add_v4(&pooled[cur * 128 + LAYER * 64 + fq * 4], sum);
                cur = g;
                sum = h;
            } else {
                sum.x += h.x; sum.y += h.y; sum.z += h.z; sum.w += h.w;
            }
        }
    }
    if (cur >= 0)
        red_add_v4(&pooled[cur * 128 + LAYER * 64 + fq * 4], sum);
}

extern "C" void kernel_launch(void* const* d_in, const int* in_sizes, int n_in,
                              void* d_out, int out_size) {
    const float* x     = (const float*)d_in[0];
    const int*   ei    = (const int*)  d_in[1];
    const int*   batch = (const int*)  d_in[2];
    const float* W1    = (const float*)d_in[3];
    const float* b1    = (const float*)d_in[4];
    const float* W2    = (const float*)d_in[5];
    const float* b2    = (const float*)d_in[6];

    float* h2     = (float*)d_out;
    float* pooled = h2 + (size_t)N_NODES * 64;

    const int TB = 256;
    const int gemmBlocks    = (N_NODES + 63) / 64;
    const int scatterBlocks = (N_EDGES * 16 + TB - 1) / TB;
    const int nodeBlocks    = (N_NODES + TB - 1) / TB;
    const int edgeBlocks    = (N_EDGES + TB - 1) / TB;

    k_init<<<nodeBlocks, TB>>>(pooled);
    k_deg <<<edgeBlocks, TB>>>(ei);

    // layer 1
    k_gemm<0><<<gemmBlocks, TB>>>(x, W1);
    k_scatter<<<scatterBlocks, TB>>>(ei);
    k_finalize<0><<<nodeBlocks, TB>>>(b1, batch, h2, pooled);

    // layer 2
    k_gemm<1><<<gemmBlocks, TB>>>(nullptr, W2);
    k_scatter<<<scatterBlocks, TB>>>(ei);
    k_finalize<1><<<nodeBlocks, TB>>>(b2, batch, h2, pooled);
}

// round 4
// speedup vs baseline: 1.3884x; 1.3884x over previous
#include <cuda_runtime.h>
#include <stdint.h>

#define N_NODES 100000
#define N_EDGES 1200000
#define NG 64
#define SCAN_ELEMS 1024
#define NBLK ((N_NODES + SCAN_ELEMS - 1) / SCAN_ELEMS)   // 98

// ---- persistent device scratch ----
__device__ float g_hs [N_NODES * 64];   // dinv-scaled X@W (gather source)
__device__ float g_h1 [N_NODES * 64];   // layer-1 activations
__device__ int   g_cnt[N_NODES];        // in-degree (no self loop)
__device__ int   g_off[N_NODES];        // CSR row start
__device__ int   g_cur[N_NODES];        // fill cursors
__device__ int   g_csrc[N_EDGES];       // src ids sorted by dst
__device__ int   g_bsum[NBLK];
__device__ int   g_boff[NBLK];

__device__ __forceinline__ void red_add_v4(float* p, float4 v) {
    asm volatile("red.global.add.v4.f32 [%0], {%1,%2,%3,%4};"
                 :: "l"(p), "f"(v.x), "f"(v.y), "f"(v.z), "f"(v.w) : "memory");
}
#define FMA_X2(d, a, b) \
    asm("fma.rn.f32x2 %0, %1, %2, %0;" : "+l"(d) : "l"(a), "l"(b))
#define PACK_DUP(d, x) \
    asm("mov.b64 %0, {%1, %1};" : "=l"(d) : "f"(x))

// ---------------- setup ----------------
__global__ void k_init(float* __restrict__ pooled) {
    int i = blockIdx.x * blockDim.x + threadIdx.x;
    if (i < N_NODES) g_cnt[i] = 0;
    if (i < NG * 128) pooled[i] = 0.0f;
}

__global__ void k_deg(const int* __restrict__ ei) {
    int e = blockIdx.x * blockDim.x + threadIdx.x;
    if (e < N_EDGES) atomicAdd(&g_cnt[ei[N_EDGES + e]], 1);
}

// per-block sums of g_cnt (1024 elems / block of 256)
__global__ __launch_bounds__(256) void k_scanA() {
    __shared__ int sS[256];
    int t = threadIdx.x, base = blockIdx.x * SCAN_ELEMS;
    int s = 0;
    #pragma unroll
    for (int j = 0; j < 4; j++) {
        int idx = base + t * 4 + j;
        if (idx < N_NODES) s += g_cnt[idx];
    }
    sS[t] = s; __syncthreads();
    for (int d = 128; d > 0; d >>= 1) {
        if (t < d) sS[t] += sS[t + d];
        __syncthreads();
    }
    if (t == 0) g_bsum[blockIdx.x] = sS[0];
}

__global__ void k_scanB() {
    if (threadIdx.x == 0) {
        int acc = 0;
        for (int b = 0; b < NBLK; b++) { int v = g_bsum[b]; g_boff[b] = acc; acc += v; }
    }
}

__global__ __launch_bounds__(256) void k_scanC() {
    __shared__ int sS[256];
    int t = threadIdx.x, base = blockIdx.x * SCAN_ELEMS;
    int c[4]; int tsum = 0;
    #pragma unroll
    for (int j = 0; j < 4; j++) {
        int idx = base + t * 4 + j;
        c[j] = (idx < N_NODES) ? g_cnt[idx] : 0;
        tsum += c[j];
    }
    sS[t] = tsum; __syncthreads();
    int run = tsum;
    for (int d = 1; d < 256; d <<= 1) {
        int v = (t >= d) ? sS[t - d] : 0;
        __syncthreads();
        run += v; sS[t] = run;
        __syncthreads();
    }
    int excl = run - tsum + g_boff[blockIdx.x];
    #pragma unroll
    for (int j = 0; j < 4; j++) {
        int idx = base + t * 4 + j;
        if (idx < N_NODES) { g_off[idx] = excl; g_cur[idx] = excl; excl += c[j]; }
    }
}

__global__ void k_fill(const int* __restrict__ ei) {
    int e = blockIdx.x * blockDim.x + threadIdx.x;
    if (e >= N_EDGES) return;
    int s = ei[e], d = ei[N_EDGES + e];
    int pos = atomicAdd(&g_cur[d], 1);
    g_csrc[pos] = s;
}

// ---------------- GEMM: hs = dinv * (X @ W), f32x2 pipes ----------------
template<int LAYER>
__global__ __launch_bounds__(256) void k_gemm(const float* __restrict__ Xin,
                                              const float* __restrict__ W) {
    __shared__ __align__(16) float sW [64 * 64];   // [k][j]
    __shared__ __align__(16) float sXT[64 * 68];   // [k][r], pitch 68
    const float* __restrict__ X = (LAYER == 0) ? Xin : (const float*)g_h1;

    const int t = threadIdx.x;
    const int rowBase = blockIdx.x * 64;

    #pragma unroll
    for (int i = 0; i < 16; i++) sW[t + i * 256] = W[t + i * 256];
    #pragma unroll
    for (int i = 0; i < 16; i++) {
        int flat = t + i * 256;
        int r = flat >> 6, k = flat & 63;
        int row = rowBase + r;
        sXT[k * 68 + r] = (row < N_NODES) ? X[row * 64 + k] : 0.0f;
    }
    __syncthreads();

    const int jq = t & 15;   // column quad
    const int rg = t >> 4;   // row group (rows rg*4 .. rg*4+3)

    uint64_t acc01[4] = {0, 0, 0, 0};   // (col j, j+1) rows 0..3
    uint64_t acc23[4] = {0, 0, 0, 0};   // (col j+2, j+3)

    const ulonglong2* sW2 = reinterpret_cast<const ulonglong2*>(sW);
    #pragma unroll 16
    for (int k = 0; k < 64; k++) {
        ulonglong2 wp = sW2[k * 16 + jq];
        float4 xv = *reinterpret_cast<const float4*>(&sXT[k * 68 + rg * 4]);
        uint64_t xx;
        PACK_DUP(xx, xv.x); FMA_X2(acc01[0], xx, wp.x); FMA_X2(acc23[0], xx, wp.y);
        PACK_DUP(xx, xv.y); FMA_X2(acc01[1], xx, wp.x); FMA_X2(acc23[1], xx, wp.y);
        PACK_DUP(xx, xv.z); FMA_X2(acc01[2], xx, wp.x); FMA_X2(acc23[2], xx, wp.y);
        PACK_DUP(xx, xv.w); FMA_X2(acc01[3], xx, wp.x); FMA_X2(acc23[3], xx, wp.y);
    }

    #pragma unroll
    for (int a = 0; a < 4; a++) {
        int row = rowBase + rg * 4 + a;
        if (row < N_NODES) {
            float dinv = rsqrtf(1.0f + (float)g_cnt[row]);
            float2 p01, p23;
            asm("mov.b64 {%0, %1}, %2;" : "=f"(p01.x), "=f"(p01.y) : "l"(acc01[a]));
            asm("mov.b64 {%0, %1}, %2;" : "=f"(p23.x), "=f"(p23.y) : "l"(acc23[a]));
            float4 o = make_float4(p01.x * dinv, p01.y * dinv, p23.x * dinv, p23.y * dinv);
            *reinterpret_cast<float4*>(&g_hs[row * 64 + jq * 4]) = o;
        }
    }
}

// ---------------- aggregation: warp per node, CSR gather ----------------
// out is selected IN DEVICE CODE (g_h1 for layer 0, d_out for layer 1).
template<int LAYER>
__global__ __launch_bounds__(256) void k_agg(const float* __restrict__ bias,
                                             float* __restrict__ h2out) {
    const int lane = threadIdx.x & 31;
    const int n = blockIdx.x * 8 + (threadIdx.x >> 5);
    if (n >= N_NODES) return;
    float* __restrict__ out = (LAYER == 0) ? (float*)g_h1 : h2out;

    const float2* __restrict__ hs2 = reinterpret_cast<const float2*>(g_hs);
    float2 v = hs2[n * 32 + lane];                 // self-loop term (pre-scaled)
    const int off = g_off[n];
    const int cnt = g_cnt[n];

    int i = 0;
    for (; i + 4 <= cnt; i += 4) {
        int s0 = g_csrc[off + i    ];
        int s1 = g_csrc[off + i + 1];
        int s2 = g_csrc[off + i + 2];
        int s3 = g_csrc[off + i + 3];
        float2 a0 = hs2[s0 * 32 + lane];
        float2 a1 = hs2[s1 * 32 + lane];
        float2 a2 = hs2[s2 * 32 + lane];
        float2 a3 = hs2[s3 * 32 + lane];
        v.x += (a0.x + a1.x) + (a2.x + a3.x);
        v.y += (a0.y + a1.y) + (a2.y + a3.y);
    }
    for (; i < cnt; i++) {
        int s = g_csrc[off + i];
        float2 a = hs2[s * 32 + lane];
        v.x += a.x; v.y += a.y;
    }

    float dinv = rsqrtf(1.0f + (float)cnt);
    float2 b = reinterpret_cast<const float2*>(bias)[lane];
    float2 h;
    h.x = fmaxf(fmaf(v.x, dinv, b.x), 0.f);
    h.y = fmaxf(fmaf(v.y, dinv, b.y), 0.f);
    reinterpret_cast<float2*>(out)[n * 32 + lane] = h;
}

// ---------------- pooling: sorted-batch running sums ----------------
// input selected IN DEVICE CODE (g_h1 for layer 0, d_out/h2 for layer 1).
template<int LAYER>
__global__ __launch_bounds__(256) void k_pool(const int* __restrict__ batch,
                                              const float* __restrict__ h2,
                                              float* __restrict__ pooled) {
    const int fq   = threadIdx.x & 15;
    const int lane = threadIdx.x >> 4;
    const int start = blockIdx.x * 256;
    const float* __restrict__ h = (LAYER == 0) ? (const float*)g_h1 : h2;

    float4 sum = make_float4(0.f, 0.f, 0.f, 0.f);
    int cur = -1;
    #pragma unroll 4
    for (int i = 0; i < 16; i++) {
        int n = start + lane + i * 16;
        if (n < N_NODES) {
            float4 hv = *reinterpret_cast<const float4*>(&h[n * 64 + fq * 4]);
            int g = batch[n];
            if (g != cur) {
                if (cur >= 0)
                    red_add_v4(&pooled[cur * 128 + LAYER * 64 + fq * 4], sum);
                cur = g;
                sum = hv;
            } else {
                sum.x += hv.x; sum.y += hv.y; sum.z += hv.z; sum.w += hv.w;
            }
        }
    }
    if (cur >= 0)
        red_add_v4(&pooled[cur * 128 + LAYER * 64 + fq * 4], sum);
}

extern "C" void kernel_launch(void* const* d_in, const int* in_sizes, int n_in,
                              void* d_out, int out_size) {
    const float* x     = (const float*)d_in[0];
    const int*   ei    = (const int*)  d_in[1];
    const int*   batch = (const int*)  d_in[2];
    const float* W1    = (const float*)d_in[3];
    const float* b1    = (const float*)d_in[4];
    const float* W2    = (const float*)d_in[5];
    const float* b2    = (const float*)d_in[6];

    float* h2     = (float*)d_out;
    float* pooled = h2 + (size_t)N_NODES * 64;

    const int TB = 256;
    const int gemmBlocks = (N_NODES + 63) / 64;
    const int nodeBlocks = (N_NODES + TB - 1) / TB;
    const int edgeBlocks = (N_EDGES + TB - 1) / TB;
    const int aggBlocks  = (N_NODES + 7) / 8;

    k_init<<<nodeBlocks, TB>>>(pooled);
    k_deg <<<edgeBlocks, TB>>>(ei);
    k_scanA<<<NBLK, TB>>>();
    k_scanB<<<1, 32>>>();
    k_scanC<<<NBLK, TB>>>();
    k_fill<<<edgeBlocks, TB>>>(ei);

    // layer 1
    k_gemm<0><<<gemmBlocks, TB>>>(x, W1);
    k_agg<0><<<aggBlocks, TB>>>(b1, h2);
    k_pool<0><<<nodeBlocks, TB>>>(batch, h2, pooled);

    // layer 2
    k_gemm<1><<<gemmBlocks, TB>>>(nullptr, W2);
    k_agg<1><<<aggBlocks, TB>>>(b2, h2);
    k_pool<1><<<nodeBlocks, TB>>>(batch, h2, pooled);
}